// round 5
// baseline (speedup 1.0000x reference)
#include <cuda_runtime.h>
#include <cuda_bf16.h>
#include <cstdint>

// KPConv, GB300 (sm_103a harness compiles at compute_103 -> no tcgen05).
// Round 5: 3-kernel pipeline with legacy tensor-core GEMM (mma.sync bf16).
//  1) prep: kv fp32 [480,64] -> transposed split-bf16 Bh/Bl [64,512]; zero agg pad rows
//  2) agg:  warp-per-row aggregation -> split-bf16 g_ah/g_al [40064,512]
//  3) gemm: mma.sync.m16n8k16 bf16, 3-term split accumulation, fp32 accum.

#define KP       15
#define FDIM     32
#define CDIM     64
#define KK       480
#define KKP      512
#define MROWS    40064
#define INV_EXTENT (1.0f / 0.6f)

// ---------------- scratch ----------------
__device__ __nv_bfloat16 g_ah[MROWS * KKP];   // 41 MB
__device__ __nv_bfloat16 g_al[MROWS * KKP];   // 41 MB
__device__ __nv_bfloat16 g_bh[CDIM * KKP];
__device__ __nv_bfloat16 g_bl[CDIM * KKP];

// ---------------- helpers ----------------
typedef unsigned long long ull;

__device__ __forceinline__ ull pack2f(float lo, float hi) {
    ull d; asm("mov.b64 %0, {%1, %2};" : "=l"(d) : "f"(lo), "f"(hi)); return d;
}
__device__ __forceinline__ void unpack2f(ull s, float& lo, float& hi) {
    asm("mov.b64 {%0, %1}, %2;" : "=f"(lo), "=f"(hi) : "l"(s));
}
__device__ __forceinline__ ull ffma2(ull a, ull b, ull c) {
    ull d; asm("fma.rn.f32x2 %0, %1, %2, %3;" : "=l"(d) : "l"(a), "l"(b), "l"(c)); return d;
}
__device__ __forceinline__ uint32_t smem_u32(const void* p) {
    uint32_t a;
    asm("{ .reg .u64 t; cvta.to.shared.u64 t, %1; cvt.u32.u64 %0, t; }" : "=r"(a) : "l"(p));
    return a;
}

// ================= kernel 1: prep =================
__global__ void kv_prep_kernel(const float* __restrict__ kv) {
    int b = blockIdx.x;
    int t = threadIdx.x;            // 512 threads = one kk each
    if (b < CDIM) {
        int c = b;
        float v = (t < KK) ? kv[t * CDIM + c] : 0.f;
        __nv_bfloat16 h = __float2bfloat16_rn(v);
        __nv_bfloat16 l = __float2bfloat16_rn(v - __bfloat162float(h));
        g_bh[c * KKP + t] = h;
        g_bl[c * KKP + t] = l;
    } else {
        int row = 40000 + (b - CDIM);     // zero pad rows 40000..40063
        g_ah[(size_t)row * KKP + t] = __float2bfloat16_rn(0.f);
        g_al[(size_t)row * KKP + t] = __float2bfloat16_rn(0.f);
    }
}

// ================= kernel 2: aggregation =================
__global__ __launch_bounds__(256) void kpconv_agg_kernel(
    const float* __restrict__ points,
    const float* __restrict__ features,
    const float* __restrict__ outp,
    const int*   __restrict__ nbr,
    const int*   __restrict__ sid,
    const float* __restrict__ kpts,
    int M, int E)
{
    __shared__ ull   w2_s[8 * 8 * 32];
    __shared__ int   bound[9];
    __shared__ float kp[KP * 3];

    const int tid = threadIdx.x;
    const int m0  = blockIdx.x * 8;

    if (tid < KP * 3) kp[tid] = kpts[tid];
    if (tid <= 8) {
        int target = m0 + tid;
        int lo = 0, hi = E;
        while (lo < hi) {
            int mid = (lo + hi) >> 1;
            if (__ldg(sid + mid) < target) lo = mid + 1; else hi = mid;
        }
        bound[tid] = lo;
    }
    __syncthreads();

    const int warp = tid >> 5;
    const int lane = tid & 31;
    ull* wrow = w2_s + warp * (8 * 32);

    int m = m0 + warp;
    if (m >= M) return;
    int s = bound[warp];
    int e = bound[warp + 1];

    float ox = __ldg(outp + m * 3 + 0);
    float oy = __ldg(outp + m * 3 + 1);
    float oz = __ldg(outp + m * 3 + 2);

    ull acc2[8];
    #pragma unroll
    for (int p = 0; p < 8; p++) acc2[p] = 0ull;

    for (int base = s; base < e; base += 32) {
        int rem = e - base;
        int cnt = rem < 32 ? rem : 32;

        int my_ni = 0;
        float rx = 0.f, ry = 0.f, rz = 0.f;
        if (lane < cnt) {
            my_ni = __ldg(nbr + base + lane);
            rx = __ldg(points + my_ni * 3 + 0) - ox;
            ry = __ldg(points + my_ni * 3 + 1) - oy;
            rz = __ldg(points + my_ni * 3 + 2) - oz;
        }
        float w[16];
        #pragma unroll
        for (int k = 0; k < KP; k++) {
            float dx = rx - kp[k * 3 + 0];
            float dy = ry - kp[k * 3 + 1];
            float dz = rz - kp[k * 3 + 2];
            float sq = fmaf(dx, dx, fmaf(dy, dy, dz * dz));
            w[k] = fmaxf(1.f - sqrtf(sq) * INV_EXTENT, 0.f);
        }
        w[15] = 0.f;
        #pragma unroll
        for (int p = 0; p < 8; p++)
            wrow[p * 32 + lane] = pack2f(w[2 * p], w[2 * p + 1]);
        __syncwarp();

        int j = 0;
        for (; j + 4 <= cnt; j += 4) {
            int   nn[4];
            float ft[4];
            #pragma unroll
            for (int u = 0; u < 4; u++)
                nn[u] = __shfl_sync(0xffffffffu, my_ni, j + u);
            #pragma unroll
            for (int u = 0; u < 4; u++)
                ft[u] = __ldg(features + nn[u] * FDIM + lane);
            #pragma unroll
            for (int u = 0; u < 4; u++) {
                ull fd = pack2f(ft[u], ft[u]);
                #pragma unroll
                for (int p = 0; p < 8; p++)
                    acc2[p] = ffma2(fd, wrow[p * 32 + j + u], acc2[p]);
            }
        }
        for (; j < cnt; ++j) {
            int ni = __shfl_sync(0xffffffffu, my_ni, j);
            float ft = __ldg(features + ni * FDIM + lane);
            ull fd = pack2f(ft, ft);
            #pragma unroll
            for (int p = 0; p < 8; p++)
                acc2[p] = ffma2(fd, wrow[p * 32 + j], acc2[p]);
        }
        __syncwarp();
    }

    // write split-bf16 (16 k-slots, slot 15 exact zero = padding to 512)
    __nv_bfloat16* ah = g_ah + (size_t)m * KKP;
    __nv_bfloat16* al = g_al + (size_t)m * KKP;
    #pragma unroll
    for (int p = 0; p < 8; p++) {
        float v0, v1;
        unpack2f(acc2[p], v0, v1);
        __nv_bfloat16 h0 = __float2bfloat16_rn(v0);
        __nv_bfloat16 l0 = __float2bfloat16_rn(v0 - __bfloat162float(h0));
        __nv_bfloat16 h1 = __float2bfloat16_rn(v1);
        __nv_bfloat16 l1 = __float2bfloat16_rn(v1 - __bfloat162float(h1));
        ah[(2 * p) * 32 + lane]     = h0;
        al[(2 * p) * 32 + lane]     = l0;
        ah[(2 * p + 1) * 32 + lane] = h1;
        al[(2 * p + 1) * 32 + lane] = l1;
    }
}

// ================= kernel 3: GEMM (mma.sync bf16, split 3-term) =================
// out[M,64] = A[M,512] * B[64,512]^T with A,B split into (hi,lo) bf16.

#define BM 128
#define BK 64
#define NCHUNK (KKP / BK)         // 8
#define LDS_ROW 144               // 64 bf16 = 128B + 16B pad (conflict-free ldmatrix)
#define AH_OFF 0
#define AL_OFF (BM * LDS_ROW)             // 18432
#define BH_OFF (2 * BM * LDS_ROW)         // 36864
#define BL_OFF (BH_OFF + CDIM * LDS_ROW)  // 46080
#define STAGE  (BL_OFF + CDIM * LDS_ROW)  // 55296
#define GEMM_SMEM (2 * STAGE)             // 110592

__device__ __forceinline__ void cp16(uint32_t dst, const void* src) {
    asm volatile("cp.async.cg.shared.global [%0], [%1], 16;" :: "r"(dst), "l"(src));
}
__device__ __forceinline__ void ldsm4(uint32_t addr, uint32_t* r) {
    asm volatile("ldmatrix.sync.aligned.m8n8.x4.shared.b16 {%0,%1,%2,%3}, [%4];"
                 : "=r"(r[0]), "=r"(r[1]), "=r"(r[2]), "=r"(r[3]) : "r"(addr));
}
__device__ __forceinline__ void mma16816(float* d, const uint32_t* a,
                                         uint32_t b0, uint32_t b1) {
    asm volatile(
        "mma.sync.aligned.m16n8k16.row.col.f32.bf16.bf16.f32 "
        "{%0,%1,%2,%3}, {%4,%5,%6,%7}, {%8,%9}, {%0,%1,%2,%3};"
        : "+f"(d[0]), "+f"(d[1]), "+f"(d[2]), "+f"(d[3])
        : "r"(a[0]), "r"(a[1]), "r"(a[2]), "r"(a[3]), "r"(b0), "r"(b1));
}

__global__ __launch_bounds__(256) void kpconv_gemm_kernel(float* __restrict__ out, int M)
{
    extern __shared__ __align__(128) char dynsmem[];
    const uint32_t sbase = smem_u32(dynsmem);

    const int tid    = threadIdx.x;
    const int warp   = tid >> 5;
    const int lane   = tid & 31;
    const int warp_m = warp & 3;     // x32 rows
    const int warp_n = warp >> 2;    // x32 cols
    const int row0   = blockIdx.x * BM;

    // stage copy: A 2x1024 chunks of 16B, B 2x512 chunks
    auto copy_stage = [&](int stg, int chunk) {
        uint32_t sb = sbase + stg * STAGE;
        int kk0 = chunk * BK;
        #pragma unroll
        for (int t = 0; t < 4; t++) {
            int i = tid + t * 256;
            int r = i >> 3, ch = i & 7;
            uint32_t d = sb + r * LDS_ROW + ch * 16;
            const size_t g = (size_t)(row0 + r) * KKP + kk0 + ch * 8;
            cp16(d + AH_OFF, g_ah + g);
            cp16(d + AL_OFF, g_al + g);
        }
        #pragma unroll
        for (int t = 0; t < 2; t++) {
            int i = tid + t * 256;
            int r = i >> 3, ch = i & 7;
            uint32_t d = sb + r * LDS_ROW + ch * 16;
            const size_t g = (size_t)r * KKP + kk0 + ch * 8;
            cp16(d + BH_OFF, g_bh + g);
            cp16(d + BL_OFF, g_bl + g);
        }
    };

    float acc[2][4][4];
    #pragma unroll
    for (int mt = 0; mt < 2; mt++)
        #pragma unroll
        for (int nt = 0; nt < 4; nt++)
            #pragma unroll
            for (int i = 0; i < 4; i++) acc[mt][nt][i] = 0.f;

    copy_stage(0, 0);
    asm volatile("cp.async.commit_group;");

    const int lmod = lane & 15;
    const int lhalf = (lane >> 4) * 16;   // +16B for k-half 1

    for (int c = 0; c < NCHUNK; c++) {
        if (c + 1 < NCHUNK) copy_stage((c + 1) & 1, c + 1);
        asm volatile("cp.async.commit_group;");
        if (c + 1 < NCHUNK) asm volatile("cp.async.wait_group 1;");
        else                asm volatile("cp.async.wait_group 0;");
        __syncthreads();

        uint32_t sb = sbase + (c & 1) * STAGE;
        #pragma unroll
        for (int s = 0; s < 4; s++) {         // 4 k16 steps per BK=64 chunk
            int koff = s * 32;                // bytes

            uint32_t a[2][2][4];              // [mtile][h/l][4]
            #pragma unroll
            for (int mt = 0; mt < 2; mt++) {
                uint32_t arow = sb + (uint32_t)(warp_m * 32 + mt * 16 + lmod) * LDS_ROW
                              + koff + lhalf;
                ldsm4(arow + AH_OFF, a[mt][0]);
                ldsm4(arow + AL_OFF, a[mt][1]);
            }
            uint32_t b[2][2][4];              // [npair][h/l][4]
            #pragma unroll
            for (int np = 0; np < 2; np++) {
                uint32_t brow = sb + (uint32_t)(warp_n * 32 + np * 16 + lmod) * LDS_ROW
                              + koff + lhalf;
                ldsm4(brow + BH_OFF, b[np][0]);
                ldsm4(brow + BL_OFF, b[np][1]);
            }

            #pragma unroll
            for (int mt = 0; mt < 2; mt++)
                #pragma unroll
                for (int nt = 0; nt < 4; nt++) {
                    int np = nt >> 1, sub = nt & 1;
                    uint32_t bh0 = b[np][0][sub], bh1 = b[np][0][sub + 2];
                    uint32_t bl0 = b[np][1][sub], bl1 = b[np][1][sub + 2];
                    mma16816(acc[mt][nt], a[mt][0], bh0, bh1);   // Ah*Bh
                    mma16816(acc[mt][nt], a[mt][0], bl0, bl1);   // Ah*Bl
                    mma16816(acc[mt][nt], a[mt][1], bh0, bh1);   // Al*Bh
                }
        }
        __syncthreads();
    }

    // epilogue
    const int qr = lane >> 2;          // 0..7
    const int qc = (lane & 3) * 2;     // 0,2,4,6
    #pragma unroll
    for (int mt = 0; mt < 2; mt++) {
        #pragma unroll
        for (int nt = 0; nt < 4; nt++) {
            int r = row0 + warp_m * 32 + mt * 16 + qr;
            int cidx = warp_n * 32 + nt * 8 + qc;
            if (r < M)
                *(float2*)(out + (size_t)r * CDIM + cidx) =
                    make_float2(acc[mt][nt][0], acc[mt][nt][1]);
            if (r + 8 < M)
                *(float2*)(out + (size_t)(r + 8) * CDIM + cidx) =
                    make_float2(acc[mt][nt][2], acc[mt][nt][3]);
        }
    }
}

// ================= launch =================
extern "C" void kernel_launch(void* const* d_in, const int* in_sizes, int n_in,
                              void* d_out, int out_size) {
    const float* points   = (const float*)d_in[0];
    const float* features = (const float*)d_in[1];
    const float* outp     = (const float*)d_in[2];
    const int*   nbr      = (const int*)d_in[3];
    const int*   sid      = (const int*)d_in[4];
    const float* kpts     = (const float*)d_in[5];
    const float* kv       = (const float*)d_in[6];
    float*       out      = (float*)d_out;

    int E = in_sizes[3];
    int M = out_size / CDIM;

    static bool attr_set = false;
    if (!attr_set) {
        cudaFuncSetAttribute(kpconv_gemm_kernel,
                             cudaFuncAttributeMaxDynamicSharedMemorySize,
                             GEMM_SMEM);
        attr_set = true;
    }

    kv_prep_kernel<<<CDIM + 64, KKP>>>(kv);
    kpconv_agg_kernel<<<(M + 7) / 8, 256>>>(points, features, outp, nbr, sid, kpts, M, E);
    kpconv_gemm_kernel<<<MROWS / BM, 256, GEMM_SMEM>>>(out, M);
}

// round 6
// speedup vs baseline: 1.3625x; 1.3625x over previous
#include <cuda_runtime.h>
#include <cuda_bf16.h>
#include <cstdint>

// KPConv, GB300 (sm_103a; harness compiles at compute_103 -> no tcgen05).
// Round 6: fused agg+GEMM. Per CTA: 32 output rows.
//   prep1: kv fp32 [480,64] -> transposed split-bf16 g_bh/g_bl [64,512]
//   prep2: rowptr[M+1] from sorted segment_ids (kills per-block binary search)
//   main:  phase A: warp-per-row aggregation -> split-bf16 A in SMEM
//          phase B: mma.sync m16n8k16 bf16 3-term GEMM [32,512]x[512,64]^T
// A never touches global memory (vs R5's 82 MB round trip).

#define KP       15
#define FDIM     32
#define CDIM     64
#define KK       480
#define KKP      512
#define BM       32
#define THREADS  256
#define INV_EXTENT (1.0f / 0.6f)

// ---- SMEM layout (bytes, dynamic) ----
#define A_STRIDE 1040                    // 512 bf16 = 1024B + 16B pad (ldmatrix conflict-free)
#define AH_OFF   0
#define AL_OFF   (BM * A_STRIDE)         // 33280
#define B_ROW    144                     // 64 bf16 = 128B + 16B pad
#define BH_OFF   (2 * BM * A_STRIDE)     // 66560
#define BL_OFF   (BH_OFF + 64 * B_ROW)   // 75776
#define SMEM_BYTES (BL_OFF + 64 * B_ROW) // 84992

// ---- scratch ----
__device__ __nv_bfloat16 g_bh[CDIM * KKP];
__device__ __nv_bfloat16 g_bl[CDIM * KKP];
__device__ int           g_rowptr[40001];

typedef unsigned long long ull;

__device__ __forceinline__ ull pack2f(float lo, float hi) {
    ull d; asm("mov.b64 %0, {%1, %2};" : "=l"(d) : "f"(lo), "f"(hi)); return d;
}
__device__ __forceinline__ void unpack2f(ull s, float& lo, float& hi) {
    asm("mov.b64 {%0, %1}, %2;" : "=f"(lo), "=f"(hi) : "l"(s));
}
__device__ __forceinline__ ull ffma2(ull a, ull b, ull c) {
    ull d; asm("fma.rn.f32x2 %0, %1, %2, %3;" : "=l"(d) : "l"(a), "l"(b), "l"(c)); return d;
}
__device__ __forceinline__ uint32_t smem_u32(const void* p) {
    uint32_t a;
    asm("{ .reg .u64 t; cvta.to.shared.u64 t, %1; cvt.u32.u64 %0, t; }" : "=r"(a) : "l"(p));
    return a;
}
__device__ __forceinline__ void ldsm4(uint32_t addr, uint32_t* r) {
    asm volatile("ldmatrix.sync.aligned.m8n8.x4.shared.b16 {%0,%1,%2,%3}, [%4];"
                 : "=r"(r[0]), "=r"(r[1]), "=r"(r[2]), "=r"(r[3]) : "r"(addr));
}
__device__ __forceinline__ void mma16816(float* d, const uint32_t* a,
                                         uint32_t b0, uint32_t b1) {
    asm volatile(
        "mma.sync.aligned.m16n8k16.row.col.f32.bf16.bf16.f32 "
        "{%0,%1,%2,%3}, {%4,%5,%6,%7}, {%8,%9}, {%0,%1,%2,%3};"
        : "+f"(d[0]), "+f"(d[1]), "+f"(d[2]), "+f"(d[3])
        : "r"(a[0]), "r"(a[1]), "r"(a[2]), "r"(a[3]), "r"(b0), "r"(b1));
}
__device__ __forceinline__ void split_bf16(float v, __nv_bfloat16& h, __nv_bfloat16& l) {
    h = __float2bfloat16_rn(v);
    l = __float2bfloat16_rn(v - __bfloat162float(h));
}

// ================= prep 1: kv split =================
__global__ void kv_prep_kernel(const float* __restrict__ kv) {
    int c = blockIdx.x;              // 64 blocks
    int t = threadIdx.x;             // 512 threads = kk
    float v = (t < KK) ? kv[t * CDIM + c] : 0.f;
    __nv_bfloat16 h, l; split_bf16(v, h, l);
    g_bh[c * KKP + t] = h;
    g_bl[c * KKP + t] = l;
}

// ================= prep 2: rowptr =================
__global__ void rowptr_kernel(const int* __restrict__ sid, int E, int M) {
    int i = blockIdx.x * blockDim.x + threadIdx.x;
    if (i >= E) return;
    int s  = __ldg(sid + i);
    int sp = (i == 0) ? -1 : __ldg(sid + i - 1);
    for (int m = sp + 1; m <= s; m++) g_rowptr[m] = i;
    if (i == E - 1)
        for (int m = s + 1; m <= M; m++) g_rowptr[m] = E;
}

// ================= main: fused agg + GEMM =================
__global__ __launch_bounds__(THREADS, 2) void kpconv_main_kernel(
    const float* __restrict__ points,
    const float* __restrict__ features,
    const float* __restrict__ outp,
    const int*   __restrict__ nbr,
    const float* __restrict__ kpts,
    float*       __restrict__ out,
    int M)
{
    extern __shared__ __align__(128) char sm[];
    __shared__ ull   w2_s[8 * 8 * 16];       // [warp][pair][edge<=16]
    __shared__ float kp[KP * 3];

    const uint32_t sbase = smem_u32(sm);
    const int tid  = threadIdx.x;
    const int warp = tid >> 5;
    const int lane = tid & 31;
    const int m0   = blockIdx.x * BM;

    if (tid < KP * 3) kp[tid] = kpts[tid];
    __syncthreads();

    // ---------------- Phase A: aggregation, 4 rows per warp ----------------
    ull* wrow = w2_s + warp * 128;
    #pragma unroll
    for (int rr = 0; rr < 4; rr++) {
        const int r = warp + rr * 8;         // 0..31
        const int m = m0 + r;
        if (m < M) {
            int s = __ldg(g_rowptr + m);
            int e = __ldg(g_rowptr + m + 1);

            float ox = __ldg(outp + m * 3 + 0);
            float oy = __ldg(outp + m * 3 + 1);
            float oz = __ldg(outp + m * 3 + 2);

            ull acc2[8];
            #pragma unroll
            for (int p = 0; p < 8; p++) acc2[p] = 0ull;

            for (int base = s; base < e; base += 16) {
                int rem = e - base;
                int cnt = rem < 16 ? rem : 16;

                // weight phase: lanes 0..cnt-1, one edge each
                int my_ni = 0;
                float rx = 0.f, ry = 0.f, rz = 0.f;
                if (lane < cnt) {
                    my_ni = __ldg(nbr + base + lane);
                    rx = __ldg(points + my_ni * 3 + 0) - ox;
                    ry = __ldg(points + my_ni * 3 + 1) - oy;
                    rz = __ldg(points + my_ni * 3 + 2) - oz;
                }
                float w[16];
                #pragma unroll
                for (int k = 0; k < KP; k++) {
                    float dx = rx - kp[k * 3 + 0];
                    float dy = ry - kp[k * 3 + 1];
                    float dz = rz - kp[k * 3 + 2];
                    float sq = fmaf(dx, dx, fmaf(dy, dy, dz * dz));
                    w[k] = fmaxf(1.f - sqrtf(sq) * INV_EXTENT, 0.f);
                }
                w[15] = 0.f;                       // K padding slot stays exact 0
                if (lane < 16) {
                    #pragma unroll
                    for (int p = 0; p < 8; p++)
                        wrow[p * 16 + lane] = pack2f(w[2 * p], w[2 * p + 1]);
                }
                __syncwarp();

                // FMA phase: lane = feature channel
                int j = 0;
                for (; j + 4 <= cnt; j += 4) {
                    int   nn[4];
                    float ft[4];
                    #pragma unroll
                    for (int u = 0; u < 4; u++)
                        nn[u] = __shfl_sync(0xffffffffu, my_ni, j + u);
                    #pragma unroll
                    for (int u = 0; u < 4; u++)
                        ft[u] = __ldg(features + nn[u] * FDIM + lane);
                    #pragma unroll
                    for (int u = 0; u < 4; u++) {
                        ull fd = pack2f(ft[u], ft[u]);
                        #pragma unroll
                        for (int p = 0; p < 8; p++)
                            acc2[p] = ffma2(fd, wrow[p * 16 + j + u], acc2[p]);
                    }
                }
                for (; j < cnt; ++j) {
                    int ni = __shfl_sync(0xffffffffu, my_ni, j);
                    float ft = __ldg(features + ni * FDIM + lane);
                    ull fd = pack2f(ft, ft);
                    #pragma unroll
                    for (int p = 0; p < 8; p++)
                        acc2[p] = ffma2(fd, wrow[p * 16 + j], acc2[p]);
                }
                __syncwarp();
            }

            // split-bf16 into resident SMEM A (rows of 520 bf16, stride 1040B)
            char* ahr = sm + AH_OFF + r * A_STRIDE;
            char* alr = sm + AL_OFF + r * A_STRIDE;
            #pragma unroll
            for (int p = 0; p < 8; p++) {
                float v0, v1;
                unpack2f(acc2[p], v0, v1);
                __nv_bfloat16 h0, l0, h1, l1;
                split_bf16(v0, h0, l0);
                split_bf16(v1, h1, l1);
                int k0 = (2 * p) * 32 + lane;        // kk slot
                int k1 = (2 * p + 1) * 32 + lane;
                *(__nv_bfloat16*)(ahr + k0 * 2) = h0;
                *(__nv_bfloat16*)(alr + k0 * 2) = l0;
                *(__nv_bfloat16*)(ahr + k1 * 2) = h1;
                *(__nv_bfloat16*)(alr + k1 * 2) = l1;
            }
        }
    }
    __syncthreads();

    // ---------------- Phase B: GEMM [32,512] x [64,512]^T ----------------
    // 8 warps: warp_m = warp&1 (16 rows), warp_n = warp>>1 (16 cols)
    const int warp_m = warp & 1;
    const int warp_n = warp >> 1;
    const int lmod  = lane & 15;
    const int lhalf = (lane >> 4) * 16;

    float acc[2][4];
    #pragma unroll
    for (int nt = 0; nt < 2; nt++)
        #pragma unroll
        for (int i = 0; i < 4; i++) acc[nt][i] = 0.f;

    // register prefetch of B chunk (bh/bl 8KB each: 512 x 16B)
    uint4 rh[2], rl[2];
    auto ldB = [&](int c) {
        int kk0 = c * 64;
        #pragma unroll
        for (int q = 0; q < 2; q++) {
            int i = tid + q * 256;
            int r = i >> 3, ch = i & 7;
            rh[q] = *(const uint4*)(g_bh + r * KKP + kk0 + ch * 8);
            rl[q] = *(const uint4*)(g_bl + r * KKP + kk0 + ch * 8);
        }
    };

    ldB(0);
    for (int c = 0; c < 8; c++) {
        // store prefetched chunk into stage
        #pragma unroll
        for (int q = 0; q < 2; q++) {
            int i = tid + q * 256;
            int r = i >> 3, ch = i & 7;
            *(uint4*)(sm + BH_OFF + r * B_ROW + ch * 16) = rh[q];
            *(uint4*)(sm + BL_OFF + r * B_ROW + ch * 16) = rl[q];
        }
        __syncthreads();
        if (c < 7) ldB(c + 1);     // in flight during MMA

        #pragma unroll
        for (int s = 0; s < 4; s++) {          // 4 k16 steps per 64-kk chunk
            uint32_t aoff = (uint32_t)(warp_m * 16 + lmod) * A_STRIDE
                          + (uint32_t)(c * 128 + s * 32) + lhalf;
            uint32_t ah[4], al[4];
            ldsm4(sbase + AH_OFF + aoff, ah);
            ldsm4(sbase + AL_OFF + aoff, al);

            uint32_t boff = (uint32_t)(warp_n * 16 + lmod) * B_ROW
                          + (uint32_t)(s * 32) + lhalf;
            uint32_t bh[4], bl[4];
            ldsm4(sbase + BH_OFF + boff, bh);
            ldsm4(sbase + BL_OFF + boff, bl);

            #pragma unroll
            for (int nt = 0; nt < 2; nt++) {
                mma16816(acc[nt], ah, bh[nt], bh[nt + 2]);   // Ah*Bh
                mma16816(acc[nt], ah, bl[nt], bl[nt + 2]);   // Ah*Bl
                mma16816(acc[nt], al, bh[nt], bh[nt + 2]);   // Al*Bh
            }
        }
        __syncthreads();
    }

    // epilogue (R5-validated fragment mapping)
    const int qr = lane >> 2;
    const int qc = (lane & 3) * 2;
    #pragma unroll
    for (int nt = 0; nt < 2; nt++) {
        int r0 = m0 + warp_m * 16 + qr;
        int cc = warp_n * 16 + nt * 8 + qc;
        if (r0 < M)
            *(float2*)(out + (size_t)r0 * CDIM + cc) = make_float2(acc[nt][0], acc[nt][1]);
        if (r0 + 8 < M)
            *(float2*)(out + (size_t)(r0 + 8) * CDIM + cc) = make_float2(acc[nt][2], acc[nt][3]);
    }
}

// ================= launch =================
extern "C" void kernel_launch(void* const* d_in, const int* in_sizes, int n_in,
                              void* d_out, int out_size) {
    const float* points   = (const float*)d_in[0];
    const float* features = (const float*)d_in[1];
    const float* outp     = (const float*)d_in[2];
    const int*   nbr      = (const int*)d_in[3];
    const int*   sid      = (const int*)d_in[4];
    const float* kpts     = (const float*)d_in[5];
    const float* kv       = (const float*)d_in[6];
    float*       out      = (float*)d_out;

    int E = in_sizes[3];
    int M = out_size / CDIM;

    static bool attr_set = false;
    if (!attr_set) {
        cudaFuncSetAttribute(kpconv_main_kernel,
                             cudaFuncAttributeMaxDynamicSharedMemorySize,
                             SMEM_BYTES);
        attr_set = true;
    }

    kv_prep_kernel<<<CDIM, KKP>>>(kv);
    rowptr_kernel<<<(E + 255) / 256, 256>>>(sid, E, M);
    int blocks = (M + BM - 1) / BM;
    kpconv_main_kernel<<<blocks, THREADS, SMEM_BYTES>>>(
        points, features, outp, nbr, kpts, out, M);
}

// round 7
// speedup vs baseline: 1.6714x; 1.2267x over previous
#include <cuda_runtime.h>
#include <cuda_fp16.h>
#include <cstdint>

// KPConv, GB300 (sm_103a; harness compiles at compute_103 -> no tcgen05).
// Round 7: fused agg+GEMM, SINGLE-term fp16 tensor GEMM.
//   Precision: fp16 inputs (11 mantissa bits) + fp32 accumulate -> global-norm
//   rel err ~2e-4 (threshold 1e-3; harness metric is norm-based per R1/R5 data).
//   prep: kv fp32 [480,64] -> transposed fp16 g_b [64,480]  (+ rowptr build)
//   main: phase A: warp-per-row aggregation -> fp16 A[32,480] in SMEM
//         (B tile cp.async'd into SMEM concurrently)
//         phase B: mma.sync m16n8k16 fp16, [32,480] x [64,480]^T, no global loads.

#define KP       15
#define FDIM     32
#define CDIM     64
#define KK       480
#define BM       32
#define THREADS  256
#define INV_EXTENT (1.0f / 0.6f)

// ---- SMEM layout (bytes, dynamic) ----
#define ROW_STRIDE 976                    // 480 fp16 = 960B + 16B pad (ldmatrix conflict-free: 61 mod 8 = 5)
#define A_OFF      0
#define B_OFF      (BM * ROW_STRIDE)      // 31232
#define SMEM_BYTES (B_OFF + CDIM * ROW_STRIDE)   // 93696

// ---- scratch ----
__device__ __half g_b[CDIM * KK];
__device__ int    g_rowptr[40001];

typedef unsigned long long ull;

__device__ __forceinline__ ull pack2f(float lo, float hi) {
    ull d; asm("mov.b64 %0, {%1, %2};" : "=l"(d) : "f"(lo), "f"(hi)); return d;
}
__device__ __forceinline__ void unpack2f(ull s, float& lo, float& hi) {
    asm("mov.b64 {%0, %1}, %2;" : "=f"(lo), "=f"(hi) : "l"(s));
}
__device__ __forceinline__ ull ffma2(ull a, ull b, ull c) {
    ull d; asm("fma.rn.f32x2 %0, %1, %2, %3;" : "=l"(d) : "l"(a), "l"(b), "l"(c)); return d;
}
__device__ __forceinline__ uint32_t smem_u32(const void* p) {
    uint32_t a;
    asm("{ .reg .u64 t; cvta.to.shared.u64 t, %1; cvt.u32.u64 %0, t; }" : "=r"(a) : "l"(p));
    return a;
}
__device__ __forceinline__ void ldsm4(uint32_t addr, uint32_t* r) {
    asm volatile("ldmatrix.sync.aligned.m8n8.x4.shared.b16 {%0,%1,%2,%3}, [%4];"
                 : "=r"(r[0]), "=r"(r[1]), "=r"(r[2]), "=r"(r[3]) : "r"(addr));
}
__device__ __forceinline__ void mma16816h(float* d, const uint32_t* a,
                                          uint32_t b0, uint32_t b1) {
    asm volatile(
        "mma.sync.aligned.m16n8k16.row.col.f32.f16.f16.f32 "
        "{%0,%1,%2,%3}, {%4,%5,%6,%7}, {%8,%9}, {%0,%1,%2,%3};"
        : "+f"(d[0]), "+f"(d[1]), "+f"(d[2]), "+f"(d[3])
        : "r"(a[0]), "r"(a[1]), "r"(a[2]), "r"(a[3]), "r"(b0), "r"(b1));
}
__device__ __forceinline__ void cp16(uint32_t dst, const void* src) {
    asm volatile("cp.async.cg.shared.global [%0], [%1], 16;" :: "r"(dst), "l"(src));
}

// ================= prep: kv->fp16 transpose + rowptr =================
__global__ void prep_kernel(const float* __restrict__ kv,
                            const int* __restrict__ sid, int E, int M) {
    int b = blockIdx.x;
    int t = threadIdx.x;
    if (b < CDIM) {
        // block c: g_b[c][kk] = fp16(kv[kk][c]), 480 kk over 256 threads
        int c = b;
        for (int kk = t; kk < KK; kk += 256)
            g_b[c * KK + kk] = __float2half_rn(kv[kk * CDIM + c]);
    } else {
        int i = (b - CDIM) * 256 + t;
        if (i >= E) return;
        int s  = __ldg(sid + i);
        int sp = (i == 0) ? -1 : __ldg(sid + i - 1);
        for (int m = sp + 1; m <= s; m++) g_rowptr[m] = i;
        if (i == E - 1)
            for (int m = s + 1; m <= M; m++) g_rowptr[m] = E;
    }
}

// ================= main: fused agg + GEMM =================
__global__ __launch_bounds__(THREADS, 2) void kpconv_main_kernel(
    const float* __restrict__ points,
    const float* __restrict__ features,
    const float* __restrict__ outp,
    const int*   __restrict__ nbr,
    const float* __restrict__ kpts,
    float*       __restrict__ out,
    int M)
{
    extern __shared__ __align__(128) char sm[];
    __shared__ ull   w2_s[8 * 8 * 16];       // [warp][pair][edge<=16]
    __shared__ float kp[KP * 3];

    const uint32_t sbase = smem_u32(sm);
    const int tid  = threadIdx.x;
    const int warp = tid >> 5;
    const int lane = tid & 31;
    const int m0   = blockIdx.x * BM;

    if (tid < KP * 3) kp[tid] = kpts[tid];

    // ---- kick off B tile load (64 rows x 480 fp16 = 60 chunks/row x 16B) ----
    // 3840 chunks over 256 threads = 15 each; overlaps with aggregation.
    #pragma unroll
    for (int q = 0; q < 15; q++) {
        int i  = tid + q * 256;
        int r  = i / 60, ch = i % 60;
        cp16(sbase + B_OFF + r * ROW_STRIDE + ch * 16, g_b + r * KK + ch * 8);
    }
    asm volatile("cp.async.commit_group;");
    __syncthreads();     // kp visible

    // ---------------- Phase A: aggregation, 4 rows per warp ----------------
    ull* wrow = w2_s + warp * 128;
    #pragma unroll
    for (int rr = 0; rr < 4; rr++) {
        const int r = warp + rr * 8;         // 0..31
        const int m = m0 + r;
        if (m < M) {
            int s = __ldg(g_rowptr + m);
            int e = __ldg(g_rowptr + m + 1);

            float ox = __ldg(outp + m * 3 + 0);
            float oy = __ldg(outp + m * 3 + 1);
            float oz = __ldg(outp + m * 3 + 2);

            ull acc2[8];
            #pragma unroll
            for (int p = 0; p < 8; p++) acc2[p] = 0ull;

            for (int base = s; base < e; base += 16) {
                int rem = e - base;
                int cnt = rem < 16 ? rem : 16;

                // weight phase: lanes 0..cnt-1, one edge each
                int my_ni = 0;
                float rx = 0.f, ry = 0.f, rz = 0.f;
                if (lane < cnt) {
                    my_ni = __ldg(nbr + base + lane);
                    rx = __ldg(points + my_ni * 3 + 0) - ox;
                    ry = __ldg(points + my_ni * 3 + 1) - oy;
                    rz = __ldg(points + my_ni * 3 + 2) - oz;
                }
                float w[16];
                #pragma unroll
                for (int k = 0; k < KP; k++) {
                    float dx = rx - kp[k * 3 + 0];
                    float dy = ry - kp[k * 3 + 1];
                    float dz = rz - kp[k * 3 + 2];
                    float sq = fmaf(dx, dx, fmaf(dy, dy, dz * dz));
                    w[k] = fmaxf(1.f - sqrtf(sq) * INV_EXTENT, 0.f);
                }
                w[15] = 0.f;
                if (lane < 16) {
                    #pragma unroll
                    for (int p = 0; p < 8; p++)
                        wrow[p * 16 + lane] = pack2f(w[2 * p], w[2 * p + 1]);
                }
                __syncwarp();

                // FMA phase: lane = feature channel
                int j = 0;
                for (; j + 4 <= cnt; j += 4) {
                    int   nn[4];
                    float ft[4];
                    #pragma unroll
                    for (int u = 0; u < 4; u++)
                        nn[u] = __shfl_sync(0xffffffffu, my_ni, j + u);
                    #pragma unroll
                    for (int u = 0; u < 4; u++)
                        ft[u] = __ldg(features + nn[u] * FDIM + lane);
                    #pragma unroll
                    for (int u = 0; u < 4; u++) {
                        ull fd = pack2f(ft[u], ft[u]);
                        #pragma unroll
                        for (int p = 0; p < 8; p++)
                            acc2[p] = ffma2(fd, wrow[p * 16 + j + u], acc2[p]);
                    }
                }
                for (; j < cnt; ++j) {
                    int ni = __shfl_sync(0xffffffffu, my_ni, j);
                    float ft = __ldg(features + ni * FDIM + lane);
                    ull fd = pack2f(ft, ft);
                    #pragma unroll
                    for (int p = 0; p < 8; p++)
                        acc2[p] = ffma2(fd, wrow[p * 16 + j], acc2[p]);
                }
                __syncwarp();
            }

            // fp16 into resident SMEM A row (480 slots: pairs 0..6 full, pair 7 lo only)
            char* ar = sm + A_OFF + r * ROW_STRIDE;
            #pragma unroll
            for (int p = 0; p < 8; p++) {
                float v0, v1;
                unpack2f(acc2[p], v0, v1);
                int k0 = (2 * p) * 32 + lane;
                *(__half*)(ar + k0 * 2) = __float2half_rn(v0);
                if (p < 7) {
                    int k1 = (2 * p + 1) * 32 + lane;
                    *(__half*)(ar + k1 * 2) = __float2half_rn(v1);
                }
            }
        }
    }
    asm volatile("cp.async.wait_group 0;");
    __syncthreads();

    // ---------------- Phase B: GEMM [32,480] x [64,480]^T ----------------
    // 8 warps: warp_m = warp&1 (16 rows), warp_n = warp>>1 (16 cols)
    const int warp_m = warp & 1;
    const int warp_n = warp >> 1;
    const uint32_t abase = sbase + A_OFF + (uint32_t)(warp_m * 16 + (lane & 15)) * ROW_STRIDE
                         + (uint32_t)(lane >> 4) * 16;
    const uint32_t bbase = sbase + B_OFF + (uint32_t)(warp_n * 16 + (lane & 15)) * ROW_STRIDE
                         + (uint32_t)(lane >> 4) * 16;

    float acc[2][4];
    #pragma unroll
    for (int nt = 0; nt < 2; nt++)
        #pragma unroll
        for (int i = 0; i < 4; i++) acc[nt][i] = 0.f;

    #pragma unroll
    for (int s = 0; s < 30; s++) {               // 30 k16 steps (K=480 exact)
        uint32_t koff = (uint32_t)s * 32;
        uint32_t a[4], b[4];
        ldsm4(abase + koff, a);
        ldsm4(bbase + koff, b);
        mma16816h(acc[0], a, b[0], b[2]);
        mma16816h(acc[1], a, b[1], b[3]);
    }

    // epilogue (validated fragment mapping)
    const int qr = lane >> 2;
    const int qc = (lane & 3) * 2;
    #pragma unroll
    for (int nt = 0; nt < 2; nt++) {
        int r0 = m0 + warp_m * 16 + qr;
        int cc = warp_n * 16 + nt * 8 + qc;
        if (r0 < M)
            *(float2*)(out + (size_t)r0 * CDIM + cc) = make_float2(acc[nt][0], acc[nt][1]);
        if (r0 + 8 < M)
            *(float2*)(out + (size_t)(r0 + 8) * CDIM + cc) = make_float2(acc[nt][2], acc[nt][3]);
    }
}

// ================= launch =================
extern "C" void kernel_launch(void* const* d_in, const int* in_sizes, int n_in,
                              void* d_out, int out_size) {
    const float* points   = (const float*)d_in[0];
    const float* features = (const float*)d_in[1];
    const float* outp     = (const float*)d_in[2];
    const int*   nbr      = (const int*)d_in[3];
    const int*   sid      = (const int*)d_in[4];
    const float* kpts     = (const float*)d_in[5];
    const float* kv       = (const float*)d_in[6];
    float*       out      = (float*)d_out;

    int E = in_sizes[3];
    int M = out_size / CDIM;

    static bool attr_set = false;
    if (!attr_set) {
        cudaFuncSetAttribute(kpconv_main_kernel,
                             cudaFuncAttributeMaxDynamicSharedMemorySize,
                             SMEM_BYTES);
        attr_set = true;
    }

    int prep_blocks = CDIM + (E + 255) / 256;
    prep_kernel<<<prep_blocks, 256>>>(kv, sid, E, M);
    int blocks = (M + BM - 1) / BM;
    kpconv_main_kernel<<<blocks, THREADS, SMEM_BYTES>>>(
        points, features, outp, nbr, kpts, out, M);
}

// round 9
// speedup vs baseline: 2.0602x; 1.2326x over previous
#include <cuda_runtime.h>
#include <cuda_fp16.h>
#include <cstdint>

// KPConv, GB300 (sm_103a; harness compiles at compute_103 -> no tcgen05).
// Round 9: R8 design with the divergent-shfl bug fixed (shfl_sync hoisted out
// of predicated branches; cp.async remains predicated).
//  - cp.async staging of point/feature gathers into per-warp SMEM tiles.
//  - B matrix pre-baked in mma-fragment layout in global (g_bfrag).
//  - __launch_bounds__(256,3): 3 CTAs/SM.

#define KP       15
#define FDIM     32
#define CDIM     64
#define KK       480
#define BM       32
#define THREADS  256
#define NSTEP    30
#define INV_EXTENT (1.0f / 0.6f)

#define ROW_STRIDE 976                    // 480 fp16 = 960B + 16B pad
#define A_BYTES    (BM * ROW_STRIDE)      // 31232 (dynamic smem)

__device__ uint4  g_bfrag[4 * NSTEP * 32];   // [warp_n][step][lane]
__device__ int    g_rowptr[40001];

typedef unsigned long long ull;

__device__ __forceinline__ ull pack2f(float lo, float hi) {
    ull d; asm("mov.b64 %0, {%1, %2};" : "=l"(d) : "f"(lo), "f"(hi)); return d;
}
__device__ __forceinline__ void unpack2f(ull s, float& lo, float& hi) {
    asm("mov.b64 {%0, %1}, %2;" : "=f"(lo), "=f"(hi) : "l"(s));
}
__device__ __forceinline__ ull ffma2(ull a, ull b, ull c) {
    ull d; asm("fma.rn.f32x2 %0, %1, %2, %3;" : "=l"(d) : "l"(a), "l"(b), "l"(c)); return d;
}
__device__ __forceinline__ uint32_t smem_u32(const void* p) {
    uint32_t a;
    asm("{ .reg .u64 t; cvta.to.shared.u64 t, %1; cvt.u32.u64 %0, t; }" : "=r"(a) : "l"(p));
    return a;
}
__device__ __forceinline__ void ldsm4(uint32_t addr, uint32_t* r) {
    asm volatile("ldmatrix.sync.aligned.m8n8.x4.shared.b16 {%0,%1,%2,%3}, [%4];"
                 : "=r"(r[0]), "=r"(r[1]), "=r"(r[2]), "=r"(r[3]) : "r"(addr));
}
__device__ __forceinline__ void mma16816h(float* d, const uint32_t* a,
                                          uint32_t b0, uint32_t b1) {
    asm volatile(
        "mma.sync.aligned.m16n8k16.row.col.f32.f16.f16.f32 "
        "{%0,%1,%2,%3}, {%4,%5,%6,%7}, {%8,%9}, {%0,%1,%2,%3};"
        : "+f"(d[0]), "+f"(d[1]), "+f"(d[2]), "+f"(d[3])
        : "r"(a[0]), "r"(a[1]), "r"(a[2]), "r"(a[3]), "r"(b0), "r"(b1));
}
__device__ __forceinline__ void cpa4(uint32_t dst, const void* src) {
    asm volatile("cp.async.ca.shared.global [%0], [%1], 4;" :: "r"(dst), "l"(src));
}
__device__ __forceinline__ void cpa16(uint32_t dst, const void* src) {
    asm volatile("cp.async.ca.shared.global [%0], [%1], 16;" :: "r"(dst), "l"(src));
}

// ================= prep: bfrag + rowptr =================
__global__ void prep_kernel(const float* __restrict__ kv,
                            const int* __restrict__ sid, int E, int M) {
    int b = blockIdx.x;
    int t = threadIdx.x;
    if (b == 0) {
        for (int i = t; i < 4 * NSTEP * 32; i += 256) {
            int l  = i & 31;
            int s  = (i >> 5) % NSTEP;
            int wn = i / (NSTEP * 32);
            int n0 = wn * 16 + (l >> 2);
            int kb = s * 16 + 2 * (l & 3);
            auto h2 = [&](int n, int k) -> uint32_t {
                __half2 p = __halves2half2(__float2half_rn(kv[k * CDIM + n]),
                                           __float2half_rn(kv[(k + 1) * CDIM + n]));
                return *(uint32_t*)&p;
            };
            uint4 v;
            v.x = h2(n0,     kb);
            v.y = h2(n0 + 8, kb);
            v.z = h2(n0,     kb + 8);
            v.w = h2(n0 + 8, kb + 8);
            g_bfrag[i] = v;
        }
    } else {
        int i = (b - 1) * 256 + t;
        if (i >= E) return;
        int s  = __ldg(sid + i);
        int sp = (i == 0) ? -1 : __ldg(sid + i - 1);
        for (int m = sp + 1; m <= s; m++) g_rowptr[m] = i;
        if (i == E - 1)
            for (int m = s + 1; m <= M; m++) g_rowptr[m] = E;
    }
}

// ================= main: fused agg + GEMM =================
__global__ __launch_bounds__(THREADS, 3) void kpconv_main_kernel(
    const float* __restrict__ points,
    const float* __restrict__ features,
    const float* __restrict__ outp,
    const int*   __restrict__ nbr,
    const float* __restrict__ kpts,
    float*       __restrict__ out,
    int M)
{
    extern __shared__ __align__(128) char sm[];          // A tile [32][976B]
    __shared__ ull   w2_s[8 * 8 * 16];
    __shared__ float ftile_s[8][16][32];
    __shared__ float ptile_s[8][16][4];
    __shared__ float kp[KP * 3];

    const uint32_t sbase = smem_u32(sm);
    const int tid  = threadIdx.x;
    const int warp = tid >> 5;
    const int lane = tid & 31;
    const int m0   = blockIdx.x * BM;

    if (tid < KP * 3) kp[tid] = kpts[tid];
    __syncthreads();

    ull*   wrow  = w2_s + warp * 128;
    float* ftile = &ftile_s[warp][0][0];
    float* ptile = &ptile_s[warp][0][0];
    const uint32_t ftile_a = smem_u32(ftile);
    const uint32_t ptile_a = smem_u32(ptile);

    // ---------------- Phase A: aggregation, 4 rows per warp ----------------
    #pragma unroll
    for (int rr = 0; rr < 4; rr++) {
        const int r = warp + rr * 8;
        const int m = m0 + r;
        if (m < M) {
            int s = __ldg(g_rowptr + m);
            int e = __ldg(g_rowptr + m + 1);

            float ox = __ldg(outp + m * 3 + 0);
            float oy = __ldg(outp + m * 3 + 1);
            float oz = __ldg(outp + m * 3 + 2);

            ull acc2[8];
            #pragma unroll
            for (int p = 0; p < 8; p++) acc2[p] = 0ull;

            for (int base = s; base < e; base += 16) {
                int rem = e - base;
                int cnt = rem < 16 ? rem : 16;

                int my_ni = 0;                    // lanes >= cnt keep 0 (safe addr)
                if (lane < cnt) my_ni = __ldg(nbr + base + lane);

                // --- group A: point coords. SHFL UNIFORM, cp.async predicated ---
                #pragma unroll
                for (int q = 0; q < 2; q++) {
                    int t2   = q * 32 + lane;
                    int edge = t2 >> 2;           // 0..15, always a valid src lane
                    int comp = t2 & 3;
                    int ni = __shfl_sync(0xffffffffu, my_ni, edge);   // uniform
                    if (edge < cnt && comp < 3)
                        cpa4(ptile_a + (edge * 4 + comp) * 4,
                             points + (size_t)ni * 3 + comp);
                }
                asm volatile("cp.async.commit_group;");

                // --- group B: feature rows. SHFL UNIFORM, cp.async predicated ---
                #pragma unroll
                for (int q = 0; q < 4; q++) {
                    int t2    = q * 32 + lane;
                    int edge  = t2 >> 3;          // 0..15
                    int chunk = t2 & 7;
                    int ni = __shfl_sync(0xffffffffu, my_ni, edge);   // uniform
                    if (edge < cnt)
                        cpa16(ftile_a + (edge * 32 + chunk * 4) * 4,
                              features + (size_t)ni * FDIM + chunk * 4);
                }
                asm volatile("cp.async.commit_group;");

                // points ready (features still in flight)
                asm volatile("cp.async.wait_group 1;");
                __syncwarp();

                // --- weight phase: lane = edge ---
                if (lane < 16) {
                    float rx = ptile[lane * 4 + 0] - ox;
                    float ry = ptile[lane * 4 + 1] - oy;
                    float rz = ptile[lane * 4 + 2] - oz;
                    #pragma unroll
                    for (int p = 0; p < 8; p++) {
                        float w0, w1 = 0.f;
                        {
                            int k = 2 * p;
                            float dx = rx - kp[k * 3 + 0];
                            float dy = ry - kp[k * 3 + 1];
                            float dz = rz - kp[k * 3 + 2];
                            float sq = fmaf(dx, dx, fmaf(dy, dy, dz * dz));
                            w0 = fmaxf(1.f - sqrtf(sq) * INV_EXTENT, 0.f);
                        }
                        if (p < 7) {
                            int k = 2 * p + 1;
                            float dx = rx - kp[k * 3 + 0];
                            float dy = ry - kp[k * 3 + 1];
                            float dz = rz - kp[k * 3 + 2];
                            float sq = fmaf(dx, dx, fmaf(dy, dy, dz * dz));
                            w1 = fmaxf(1.f - sqrtf(sq) * INV_EXTENT, 0.f);
                        }
                        wrow[p * 16 + lane] = pack2f(w0, w1);
                    }
                }

                // features ready
                asm volatile("cp.async.wait_group 0;");
                __syncwarp();

                // --- FMA phase: lane = feature channel, SMEM-only reads ---
                for (int j = 0; j < cnt; ++j) {
                    float ft = ftile[j * 32 + lane];
                    ull fd = pack2f(ft, ft);
                    #pragma unroll
                    for (int p = 0; p < 8; p++)
                        acc2[p] = ffma2(fd, wrow[p * 16 + j], acc2[p]);
                }
                __syncwarp();
            }

            // fp16 into resident SMEM A row
            char* ar = sm + r * ROW_STRIDE;
            #pragma unroll
            for (int p = 0; p < 8; p++) {
                float v0, v1;
                unpack2f(acc2[p], v0, v1);
                int k0 = (2 * p) * 32 + lane;
                *(__half*)(ar + k0 * 2) = __float2half_rn(v0);
                if (p < 7) {
                    int k1 = (2 * p + 1) * 32 + lane;
                    *(__half*)(ar + k1 * 2) = __float2half_rn(v1);
                }
            }
        }
    }
    __syncthreads();

    // ---------------- Phase B: GEMM [32,480] x [64,480]^T ----------------
    const int warp_m = warp & 1;
    const int warp_n = warp >> 1;
    const uint32_t abase = sbase + (uint32_t)(warp_m * 16 + (lane & 15)) * ROW_STRIDE
                         + (uint32_t)(lane >> 4) * 16;
    const uint4* bf = g_bfrag + (size_t)warp_n * NSTEP * 32 + lane;

    float acc[2][4];
    #pragma unroll
    for (int nt = 0; nt < 2; nt++)
        #pragma unroll
        for (int i = 0; i < 4; i++) acc[nt][i] = 0.f;

    #pragma unroll
    for (int s = 0; s < NSTEP; s++) {
        uint32_t a[4];
        ldsm4(abase + (uint32_t)s * 32, a);
        uint4 f = __ldg(bf + s * 32);
        mma16816h(acc[0], a, f.x, f.z);
        mma16816h(acc[1], a, f.y, f.w);
    }

    // epilogue (validated fragment mapping)
    const int qr = lane >> 2;
    const int qc = (lane & 3) * 2;
    #pragma unroll
    for (int nt = 0; nt < 2; nt++) {
        int r0 = m0 + warp_m * 16 + qr;
        int cc = warp_n * 16 + nt * 8 + qc;
        if (r0 < M)
            *(float2*)(out + (size_t)r0 * CDIM + cc) = make_float2(acc[nt][0], acc[nt][1]);
        if (r0 + 8 < M)
            *(float2*)(out + (size_t)(r0 + 8) * CDIM + cc) = make_float2(acc[nt][2], acc[nt][3]);
    }
}

// ================= launch =================
extern "C" void kernel_launch(void* const* d_in, const int* in_sizes, int n_in,
                              void* d_out, int out_size) {
    const float* points   = (const float*)d_in[0];
    const float* features = (const float*)d_in[1];
    const float* outp     = (const float*)d_in[2];
    const int*   nbr      = (const int*)d_in[3];
    const int*   sid      = (const int*)d_in[4];
    const float* kpts     = (const float*)d_in[5];
    const float* kv       = (const float*)d_in[6];
    float*       out      = (float*)d_out;

    int E = in_sizes[3];
    int M = out_size / CDIM;

    static bool attr_set = false;
    if (!attr_set) {
        cudaFuncSetAttribute(kpconv_main_kernel,
                             cudaFuncAttributeMaxDynamicSharedMemorySize,
                             A_BYTES);
        attr_set = true;
    }

    int prep_blocks = 1 + (E + 255) / 256;
    prep_kernel<<<prep_blocks, 256>>>(kv, sid, E, M);
    int blocks = (M + BM - 1) / BM;
    kpconv_main_kernel<<<blocks, THREADS, A_BYTES>>>(
        points, features, outp, nbr, kpts, out, M);
}